// round 9
// baseline (speedup 1.0000x reference)
#include <cuda_runtime.h>
#include <cuda_bf16.h>
#include <math.h>
#include <float.h>

#define Bn 2
#define Sn 1024
#define HIDn 2048
#define NHn 16
#define NKVn 8
#define Dn 128
#define Mn (Bn*Sn)
#define QNn (NHn*Dn)
#define KNn (NKVn*Dn)
#define FQEPS 1.5259021896696422e-09f
#define N_HS (Mn*HIDn)
#define N_Q  (Mn*QNn)
#define N_K  (Mn*KNn)
#define N_SC ((size_t)Bn*NHn*Sn*Sn)
#define NROWS (Bn*NHn*Sn)
#define OUT_MAIN (Mn*HIDn)
#define NW1 (QNn*HIDn)
#define NW2 (NW1+KNn*HIDn)
#define NW3 (NW2+KNn*HIDn)
#define NW4 (NW3+HIDn*QNn)
#define WALL (NW3)

enum {S_HS=0,S_QLIN,S_QRMS,S_QRMS2,S_KLIN,S_KRMS,S_KRMS2,S_QP1,S_QP2,S_QSUM,
      S_KP1,S_KP2,S_KSUM,S_V,S_SC,S_AMIN,S_AMIN2,S_UNM,S_P,S_CTX,NSLOT};

__device__ float g_red[2*NSLOT];
__device__ float g_lin[N_Q];
__device__ float g_link[N_K];
__device__ float g_qr[N_Q];
__device__ float g_kr[N_K];
__device__ float g_v[N_K];
__device__ float g_ctx[N_Q];
__device__ float g_scores[N_SC];
__device__ float g_amin[NROWS];
__device__ __nv_bfloat16 g_hsh[N_HS], g_hsl[N_HS];
__device__ __nv_bfloat16 g_wAh[WALL], g_wAl[WALL];
__device__ __nv_bfloat16 g_woh[HIDn*QNn], g_wol[HIDn*QNn];
__device__ __nv_bfloat16 g_qh[N_Q], g_ql[N_Q];
__device__ __nv_bfloat16 g_kq8[N_K];
__device__ __nv_bfloat16 g_vq8[N_K];
__device__ __nv_bfloat16 g_ch[N_Q], g_cl[N_Q];

__device__ __forceinline__ void atomicMinF(float* a,float v){
  int* ai=(int*)a; int cur=*ai;
  while(v<__int_as_float(cur)){int old=atomicCAS(ai,cur,__float_as_int(v)); if(old==cur)break; cur=old;}
}
__device__ __forceinline__ void atomicMaxF(float* a,float v){
  int* ai=(int*)a; int cur=*ai;
  while(v>__int_as_float(cur)){int old=atomicCAS(ai,cur,__float_as_int(v)); if(old==cur)break; cur=old;}
}
__device__ __forceinline__ float warp_min(float v){
  #pragma unroll
  for(int o=16;o;o>>=1) v=fminf(v,__shfl_xor_sync(0xffffffffu,v,o));
  return v;
}
__device__ __forceinline__ float warp_max(float v){
  #pragma unroll
  for(int o=16;o;o>>=1) v=fmaxf(v,__shfl_xor_sync(0xffffffffu,v,o));
  return v;
}
__device__ __forceinline__ float warp_sum(float v){
  #pragma unroll
  for(int o=16;o;o>>=1) v+=__shfl_xor_sync(0xffffffffu,v,o);
  return v;
}
__device__ __forceinline__ void red_minmax_atomic(float lmn,float lmx,int slot){
  __shared__ float smn[8],smx[8];
  lmn=warp_min(lmn); lmx=warp_max(lmx);
  int lane=threadIdx.x&31,w=threadIdx.x>>5,nw=(blockDim.x+31)>>5;
  __syncthreads();
  if(lane==0){smn[w]=lmn;smx[w]=lmx;}
  __syncthreads();
  if(w==0){
    lmn=(lane<nw)?smn[lane]:FLT_MAX;
    lmx=(lane<nw)?smx[lane]:-FLT_MAX;
    lmn=warp_min(lmn); lmx=warp_max(lmx);
    if(lane==0){atomicMinF(&g_red[2*slot],lmn); atomicMaxF(&g_red[2*slot+1],lmx);}
  }
}
__device__ __forceinline__ float blk_max_b(float v){
  __shared__ float sh[8]; __shared__ float r;
  v=warp_max(v);
  int lane=threadIdx.x&31,w=threadIdx.x>>5,nw=(blockDim.x+31)>>5;
  __syncthreads();
  if(lane==0) sh[w]=v;
  __syncthreads();
  if(threadIdx.x==0){float m=-FLT_MAX; for(int i=0;i<nw;i++)m=fmaxf(m,sh[i]); r=m;}
  __syncthreads();
  return r;
}
__device__ __forceinline__ float blk_sum_b(float v){
  __shared__ float sh[8]; __shared__ float r;
  v=warp_sum(v);
  int lane=threadIdx.x&31,w=threadIdx.x>>5,nw=(blockDim.x+31)>>5;
  __syncthreads();
  if(lane==0) sh[w]=v;
  __syncthreads();
  if(threadIdx.x==0){float m=0.f; for(int i=0;i<nw;i++)m+=sh[i]; r=m;}
  __syncthreads();
  return r;
}
__device__ __forceinline__ float fq_range_d(float x,float mn,float mx){
  float scale=fmaxf((mx-mn)/65535.0f,FQEPS);
  float zp=rintf(-mn/scale);
  float q=fminf(fmaxf(rintf(x/scale)+zp,0.0f),65535.0f);
  return (q-zp)*scale;
}
__device__ __forceinline__ void get_params(int t,int s,float&a0,float&a1,float&a2){
  float mn=g_red[2*s],mx=g_red[2*s+1];
  a0=fminf(mn,0.f); a1=fmaxf(mx,0.f); a2=1;
  if(t==2){
    float lo=fq_range_d(mn,a0,a1),hi=fq_range_d(mx,a0,a1);
    a2=fmaxf(fmaxf(fabsf(lo),fabsf(hi))/127.0f,1e-12f);
  }
}
__device__ __forceinline__ void split_bf(float v,__nv_bfloat16& h,__nv_bfloat16& l){
  h=__float2bfloat16_rn(v);
  l=__float2bfloat16_rn(v-__bfloat162float(h));
}
__device__ __forceinline__ unsigned sptr(const void* p){
  return (unsigned)__cvta_generic_to_shared(p);
}
__device__ __forceinline__ void ldsm4(unsigned* r, unsigned addr){
  asm volatile("ldmatrix.sync.aligned.m8n8.x4.shared.b16 {%0,%1,%2,%3},[%4];"
    : "=r"(r[0]),"=r"(r[1]),"=r"(r[2]),"=r"(r[3]) : "r"(addr));
}
__device__ __forceinline__ void ldsm4t(unsigned* r, unsigned addr){
  asm volatile("ldmatrix.sync.aligned.m8n8.x4.trans.shared.b16 {%0,%1,%2,%3},[%4];"
    : "=r"(r[0]),"=r"(r[1]),"=r"(r[2]),"=r"(r[3]) : "r"(addr));
}
__device__ __forceinline__ void cpa16(void* s,const void* g){
  asm volatile("cp.async.cg.shared.global [%0],[%1],16;"::"r"(sptr(s)),"l"(g));
}
#define CPCOMMIT() asm volatile("cp.async.commit_group;")
#define CPWAIT1()  asm volatile("cp.async.wait_group 1;")
#define MMA16816(d,a,b0,b1) \
  asm volatile("mma.sync.aligned.m16n8k16.row.col.f32.bf16.bf16.f32 " \
    "{%0,%1,%2,%3},{%4,%5,%6,%7},{%8,%9},{%0,%1,%2,%3};" \
    : "+f"(d[0]),"+f"(d[1]),"+f"(d[2]),"+f"(d[3]) \
    : "r"(a[0]),"r"(a[1]),"r"(a[2]),"r"(a[3]),"r"(b0),"r"(b1))

__global__ void k_init(float* __restrict__ amin){
  int gid=blockIdx.x*256+threadIdx.x;
  if(gid<NSLOT){g_red[2*gid]=FLT_MAX; g_red[2*gid+1]=-FLT_MAX;}
  amin[gid]=FLT_MAX;
}
// all four weights, one launch; segments 32-aligned so each warp stays in one weight
__global__ void k_wsplit4(const float* __restrict__ Wq,const float* __restrict__ Wk,
                          const float* __restrict__ Wv,const float* __restrict__ Wo,
                          __nv_bfloat16* __restrict__ wAh,__nv_bfloat16* __restrict__ wAl,
                          __nv_bfloat16* __restrict__ woh,__nv_bfloat16* __restrict__ wol){
  int g=blockIdx.x*256+threadIdx.x;
  float w;
  if(g<NW1) w=Wq[g];
  else if(g<NW2) w=Wk[g-NW1];
  else if(g<NW3) w=Wv[g-NW2];
  else w=Wo[g-NW3];
  float a=fabsf(w);
  #pragma unroll
  for(int o=16;o;o>>=1) a=fmaxf(a,__shfl_xor_sync(0xffffffffu,a,o));
  float s=fmaxf(a/7.0f,1e-12f);
  float v=fminf(fmaxf(rintf(w/s),-8.0f),7.0f)*s;
  __nv_bfloat16 hh,ll; split_bf(v,hh,ll);
  if(g<NW3){wAh[g]=hh; wAl[g]=ll;}
  else {woh[g-NW3]=hh; wol[g-NW3]=ll;}
}
__global__ void k_minmax(const float* __restrict__ x,int n,int slot){
  int i=blockIdx.x*blockDim.x+threadIdx.x, st=gridDim.x*blockDim.x;
  float lmn=FLT_MAX,lmx=-FLT_MAX;
  for(;i<n;i+=st){float v=x[i]; lmn=fminf(lmn,v); lmx=fmaxf(lmx,v);}
  red_minmax_atomic(lmn,lmx,slot);
}
__global__ void k_fqsplit(const float* __restrict__ in,__nv_bfloat16* __restrict__ hi,
                          __nv_bfloat16* __restrict__ lo,int n,int slot){
  float a0,a1,a2; get_params(1,slot,a0,a1,a2);
  int i=blockIdx.x*blockDim.x+threadIdx.x, st=gridDim.x*blockDim.x;
  for(;i<n;i+=st){
    float v=fq_range_d(in[i],a0,a1);
    split_bf(v,hi[i],lo[i]);
  }
}
__global__ void k_fq8q(const float* __restrict__ in,__nv_bfloat16* __restrict__ q8,
                       int n,int slot){
  float a0,a1,a2; get_params(2,slot,a0,a1,a2);
  int i=blockIdx.x*blockDim.x+threadIdx.x, st=gridDim.x*blockDim.x;
  for(;i<n;i+=st){
    float v=fq_range_d(in[i],a0,a1);
    float q=fminf(fmaxf(rintf(v/a2),-128.f),127.f);
    q8[i]=__float2bfloat16_rn(q);
  }
}
// per-row attn output: masked positions share one constant (exact div for unmasked)
__global__ void k_pattn(const float* __restrict__ sc,float* __restrict__ attn){
  int row=blockIdx.x; int s=row%Sn;
  float a0,a1,a2; get_params(1,S_P,a0,a1,a2);
  size_t base=(size_t)row*Sn;
  float pmq=0.f;
  if(s<Sn-1) pmq=fq_range_d(sc[base+Sn-1],a0,a1);
  int t0=threadIdx.x*4;
  float o[4];
  if(t0<=s){
    float4 x=*(const float4*)&sc[base+t0];
    float xi[4]={x.x,x.y,x.z,x.w};
    #pragma unroll
    for(int j=0;j<4;j++) o[j]=(t0+j<=s)?fq_range_d(xi[j],a0,a1):pmq;
  } else {
    o[0]=o[1]=o[2]=o[3]=pmq;
  }
  *(float4*)&attn[base+t0]=make_float4(o[0],o[1],o[2],o[3]);
}
__global__ void k_rms(float* __restrict__ x,const float* __restrict__ w,
                      int sIn,int sOut,int sOut2){
  int row=blockIdx.x,d=threadIdx.x;
  float mn=fminf(g_red[2*sIn],0.f),mx=fmaxf(g_red[2*sIn+1],0.f);
  size_t idx=(size_t)row*Dn+d;
  float v=fq_range_d(x[idx],mn,mx);
  float s=warp_sum(v*v);
  __shared__ float sh[4];
  if((d&31)==0) sh[d>>5]=s;
  __syncthreads();
  float var=(sh[0]+sh[1]+sh[2]+sh[3])*(1.0f/128.0f);
  float y=v*(1.0f/sqrtf(var+1e-6f))*w[d];
  x[idx]=y;
  red_minmax_atomic(y,y,sOut);
  float m2n=(d>=64)?y:FLT_MAX, m2x=(d>=64)?y:-FLT_MAX;
  red_minmax_atomic(m2n,m2x,sOut2);
}
#define ROPE_CONSTS \
  float mnY=g_red[2*sRMS],mxY=g_red[2*sRMS+1]; \
  float c10=fminf(mnY,0.f),c11=fmaxf(mxY,0.f); \
  float amn=fq_range_d(mnY,c10,c11),amx=fq_range_d(mxY,c10,c11); \
  float c20=fminf(amn,0.f),c21=fmaxf(amx,0.f); \
  float y2n=g_red[2*sRMS2],y2x=g_red[2*sRMS2+1]; \
  float x2n=fq_range_d(fq_range_d(y2n,c10,c11),c20,c21); \
  float x2x=fq_range_d(fq_range_d(y2x,c10,c11),c20,c21); \
  float nTn=-x2x,nTx=-x2n; \
  float n0=fminf(nTn,0.f),n1=fmaxf(nTx,0.f); \
  float negLo=fq_range_d(nTn,n0,n1),negHi=fq_range_d(nTx,n0,n1); \
  float qbMn=fq_range_d(amn,c20,c21),qbMx=fq_range_d(amx,c20,c21); \
  float cc0=fminf(fminf(qbMn,negLo),0.f),cc1=fmaxf(fmaxf(qbMx,negHi),0.f);
#define ROPE_BODY(QB,ROT) \
    float QB=fq_range_d(fq_range_d(y[i],c10,c11),c20,c21); \
    float ROT; \
    if(d<64){ \
      float qbp=fq_range_d(fq_range_d(y[i+64],c10,c11),c20,c21); \
      ROT=fq_range_d(fq_range_d(-qbp,n0,n1),cc0,cc1); \
    } else { \
      float qbp=fq_range_d(fq_range_d(y[i-64],c10,c11),c20,c21); \
      ROT=fq_range_d(qbp,cc0,cc1); \
    }
__global__ void k_rope1(const float* __restrict__ y,const float* __restrict__ cosb,
                        const float* __restrict__ sinb,int H,int n,
                        int sRMS,int sRMS2,int sP1,int sP2){
  ROPE_CONSTS
  int i0=blockIdx.x*blockDim.x+threadIdx.x, st=gridDim.x*blockDim.x;
  float l1n=FLT_MAX,l1x=-FLT_MAX,l2n=FLT_MAX,l2x=-FLT_MAX;
  for(int i=i0;i<n;i+=st){
    int d=i%Dn; int r=i/Dn; int s=(r/H)%Sn; int b=r/(H*Sn);
    ROPE_BODY(qb,rot)
    int ci=(b*Sn+s)*Dn+d;
    float v1=qb*cosb[ci], v2=rot*sinb[ci];
    l1n=fminf(l1n,v1); l1x=fmaxf(l1x,v1);
    l2n=fminf(l2n,v2); l2x=fmaxf(l2x,v2);
  }
  red_minmax_atomic(l1n,l1x,sP1);
  red_minmax_atomic(l2n,l2x,sP2);
}
__global__ void k_rope2(const float* __restrict__ y,const float* __restrict__ cosb,
                        const float* __restrict__ sinb,float* __restrict__ out,
                        int H,int n,int sRMS,int sRMS2,int sP1,int sP2,int sSum){
  ROPE_CONSTS
  float a0=fminf(g_red[2*sP1],0.f),a1=fmaxf(g_red[2*sP1+1],0.f);
  float b0=fminf(g_red[2*sP2],0.f),b1=fmaxf(g_red[2*sP2+1],0.f);
  int i0=blockIdx.x*blockDim.x+threadIdx.x, st=gridDim.x*blockDim.x;
  float lmn=FLT_MAX,lmx=-FLT_MAX;
  for(int i=i0;i<n;i+=st){
    int d=i%Dn; int r=i/Dn; int h=r%H; int s=(r/H)%Sn; int b=r/(H*Sn);
    ROPE_BODY(qb,rot)
    int ci=(b*Sn+s)*Dn+d;
    float v1=qb*cosb[ci], v2=rot*sinb[ci];
    float v=fq_range_d(v1,a0,a1)+fq_range_d(v2,b0,b1);
    out[((size_t)(b*H+h)*Sn+s)*Dn+d]=v;
    lmn=fminf(lmn,v); lmx=fmaxf(lmx,v);
  }
  red_minmax_atomic(lmn,lmx,sSum);
}

#define ASZ (128*40)
#define VSZ (32*136)
#define FSZ (128*32)

// ---------- fused Q/K/V projection GEMM (one launch, combined weights) ----------
__global__ __launch_bounds__(256) void mma_qkv(
  const __nv_bfloat16* __restrict__ Ah,const __nv_bfloat16* __restrict__ Al,
  const __nv_bfloat16* __restrict__ Bh,const __nv_bfloat16* __restrict__ Bl,
  float* __restrict__ Cq,float* __restrict__ Ck,float* __restrict__ Cv)
{
  extern __shared__ __nv_bfloat16 sm[];
  __nv_bfloat16* Abase=sm;
  __nv_bfloat16* Bbase=sm+4*ASZ;
  int tid=threadIdx.x, lane=tid&31, w=tid>>5;
  int wm=(w&3)*32, wn=(w>>2)*64;
  int g=lane>>2, t4=lane&3;
  int m0=blockIdx.y*128, n0=blockIdx.x*128;
  int mat=lane>>3, mrow=lane&7;
  float acc[2][8][4];
  #pragma unroll
  for(int i=0;i<2;i++)
    #pragma unroll
    for(int j=0;j<8;j++)
      #pragma unroll
      for(int r=0;r<4;r++) acc[i][j][r]=0.f;
  auto loadST=[&](int st,int k0){
    #pragma unroll
    for(int rep=0;rep<2;rep++){
      int c=tid+rep*256; int row=c>>2, col=(c&3)*8;
      cpa16(&Abase[(st*2+0)*ASZ+row*40+col],Ah+(size_t)(m0+row)*HIDn+k0+col);
      cpa16(&Abase[(st*2+1)*ASZ+row*40+col],Al+(size_t)(m0+row)*HIDn+k0+col);
      cpa16(&Bbase[(st*2+0)*ASZ+row*40+col],Bh+(size_t)(n0+row)*HIDn+k0+col);
      cpa16(&Bbase[(st*2+1)*ASZ+row*40+col],Bl+(size_t)(n0+row)*HIDn+k0+col);
    }
  };
  int niter=HIDn/32;
  loadST(0,0); CPCOMMIT();
  loadST(1,32); CPCOMMIT();
  for(int i=0;i<niter;i++){
    CPWAIT1(); __syncthreads();
    int st=i&1;
    const __nv_bfloat16* As0=Abase+(st*2+0)*ASZ;
    const __nv_bfloat16* As1=Abase+(st*2+1)*ASZ;
    const __nv_bfloat16* Bs0=Bbase+(st*2+0)*ASZ;
    const __nv_bfloat16* Bs1=Bbase+(st*2+1)*ASZ;
    #pragma unroll
    for(int kk=0;kk<32;kk+=16){
      unsigned af[2][2][4];
      #pragma unroll
      for(int mt=0;mt<2;mt++){
        ldsm4(af[mt][0],sptr(&As0[(wm+mt*16+(mat&1)*8+mrow)*40 + kk + (mat>>1)*8]));
        ldsm4(af[mt][1],sptr(&As1[(wm+mt*16+(mat&1)*8+mrow)*40 + kk + (mat>>1)*8]));
      }
      unsigned bf[8][2];
      #pragma unroll
      for(int hf=0;hf<4;hf++){
        unsigned r[4];
        ldsm4(r,sptr(&Bs0[(wn+hf*16+(mat&1)*8+mrow)*40 + kk + (mat>>1)*8]));
        bf[hf*2+0][0]=r[0]; bf[hf*2+1][0]=r[1];
        bf[hf*2+0][1]=r[2]; bf[hf*2+1][1]=r[3];
      }
      #pragma unroll
      for(int mt=0;mt<2;mt++)
        #pragma unroll
        for(int nt=0;nt<8;nt++){
          MMA16816(acc[mt][nt],af[mt][0],bf[nt][0],bf[nt][1]);
          MMA16816(acc[mt][nt],af[mt][1],bf[nt][0],bf[nt][1]);
        }
      #pragma unroll
      for(int hf=0;hf<4;hf++){
        unsigned r[4];
        ldsm4(r,sptr(&Bs1[(wn+hf*16+(mat&1)*8+mrow)*40 + kk + (mat>>1)*8]));
        bf[hf*2+0][0]=r[0]; bf[hf*2+1][0]=r[1];
        bf[hf*2+0][1]=r[2]; bf[hf*2+1][1]=r[3];
      }
      #pragma unroll
      for(int mt=0;mt<2;mt++)
        #pragma unroll
        for(int nt=0;nt<8;nt++)
          MMA16816(acc[mt][nt],af[mt][0],bf[nt][0],bf[nt][1]);
    }
    __syncthreads();
    if(i+2<niter) loadST(st,(i+2)*32);
    CPCOMMIT();
  }
  // epilogue select by output region
  int xb=blockIdx.x;
  float* Csel; int ldcs,c0,slot;
  if(xb<16){Csel=Cq; ldcs=QNn; c0=xb*128; slot=S_QLIN;}
  else if(xb<24){Csel=Ck; ldcs=KNn; c0=(xb-16)*128; slot=S_KLIN;}
  else {Csel=Cv; ldcs=KNn; c0=(xb-24)*128; slot=S_V;}
  float lmn=FLT_MAX,lmx=-FLT_MAX;
  #pragma unroll
  for(int mt=0;mt<2;mt++)
    #pragma unroll
    for(int nt=0;nt<8;nt++){
      int r0=m0+wm+mt*16+g, c=c0+wn+nt*8+t4*2;
      float v0=acc[mt][nt][0],v1=acc[mt][nt][1],v2=acc[mt][nt][2],v3=acc[mt][nt][3];
      Csel[(size_t)r0*ldcs+c]=v0; Csel[(size_t)r0*ldcs+c+1]=v1;
      Csel[(size_t)(r0+8)*ldcs+c]=v2; Csel[(size_t)(r0+8)*ldcs+c+1]=v3;
      lmn=fminf(fminf(lmn,fminf(v0,v1)),fminf(v2,v3));
      lmx=fmaxf(fmaxf(lmx,fmaxf(v0,v1)),fmaxf(v2,v3));
    }
  red_minmax_atomic(lmn,lmx,slot);
}

// ---------- 128x128 double-buffered bf16 mma.sync NT GEMM ----------
template<bool UBL>
__global__ __launch_bounds__(256) void mma_nt(
  const __nv_bfloat16* __restrict__ Ah,const __nv_bfloat16* __restrict__ Al,
  const __nv_bfloat16* __restrict__ Bh,const __nv_bfloat16* __restrict__ Bl,
  float* __restrict__ C,int K,int lda,int ldb,int ldc,
  int sOut,int scaleSlot,int batch)
{
  extern __shared__ __nv_bfloat16 sm[];
  __nv_bfloat16* Abase=sm;
  __nv_bfloat16* Bbase=sm+4*ASZ;
  int z=blockIdx.z;
  if(batch==1){
    int b=z>>4,h=z&15;
    size_t ao=(size_t)z*Sn*Dn, bo=(size_t)(b*NKVn+(h>>1))*Sn*Dn, co=(size_t)z*Sn*Sn;
    Ah+=ao; Al+=ao; Bh+=bo; Bl+=bo; C+=co;
  }
  int tid=threadIdx.x, lane=tid&31, w=tid>>5;
  int wm=(w&3)*32, wn=(w>>2)*64;
  int g=lane>>2, t4=lane&3;
  int m0=blockIdx.y*128, n0=blockIdx.x*128;
  int mat=lane>>3, mrow=lane&7;
  float acc[2][8][4];
  #pragma unroll
  for(int i=0;i<2;i++)
    #pragma unroll
    for(int j=0;j<8;j++)
      #pragma unroll
      for(int r=0;r<4;r++) acc[i][j][r]=0.f;
  auto loadST=[&](int st,int k0){
    #pragma unroll
    for(int rep=0;rep<2;rep++){
      int c=tid+rep*256; int row=c>>2, col=(c&3)*8;
      cpa16(&Abase[(st*2+0)*ASZ+row*40+col],Ah+(size_t)(m0+row)*lda+k0+col);
      cpa16(&Abase[(st*2+1)*ASZ+row*40+col],Al+(size_t)(m0+row)*lda+k0+col);
      cpa16(&Bbase[(UBL?(st*2):st)*ASZ+row*40+col],Bh+(size_t)(n0+row)*ldb+k0+col);
      if(UBL) cpa16(&Bbase[(st*2+1)*ASZ+row*40+col],Bl+(size_t)(n0+row)*ldb+k0+col);
    }
  };
  int niter=K/32;
  loadST(0,0); CPCOMMIT();
  loadST(1,32); CPCOMMIT();
  for(int i=0;i<niter;i++){
    CPWAIT1(); __syncthreads();
    int st=i&1;
    const __nv_bfloat16* As0=Abase+(st*2+0)*ASZ;
    const __nv_bfloat16* As1=Abase+(st*2+1)*ASZ;
    const __nv_bfloat16* Bs0=Bbase+(UBL?(st*2):st)*ASZ;
    const __nv_bfloat16* Bs1=UBL?(Bbase+(st*2+1)*ASZ):Bs0;
    #pragma unroll
    for(int kk=0;kk<32;kk+=16){
      unsigned af[2][2][4];
      #pragma unroll
      for(int mt=0;mt<2;mt++){
        ldsm4(af[mt][0],sptr(&As0[(wm+mt*16+(mat&1)*8+mrow)*40 + kk + (mat>>1)*8]));
        ldsm4(af[mt][1],sptr(&As1[(wm+mt*16+(mat&1)*8+mrow)*40 + kk + (mat>>1)*8]));
      }
      unsigned bf[8][2];
      #pragma unroll
      for(int hf=0;hf<4;hf++){
        unsigned r[4];
        ldsm4(r,sptr(&Bs0[(wn+hf*16+(mat&1)*8+mrow)*40 + kk + (mat>>1)*8]));
        bf[hf*2+0][0]=r[0]; bf[hf*2+1][0]=r[1];
        bf[hf*2+0][1]=r[2]; bf[hf*2+1][1]=r[3];
      }
      #pragma unroll
      for(int mt=0;mt<2;mt++)
        #pragma unroll
        for(int nt=0;nt<8;nt++){
          MMA16816(acc[mt][nt],af[mt][0],bf[nt][0],bf[nt][1]);
          MMA16816(acc[mt][nt],af[mt][1],bf[nt][0],bf[nt][1]);
        }
      if(UBL){
        #pragma unroll
        for(int hf=0;hf<4;hf++){
          unsigned r[4];
          ldsm4(r,sptr(&Bs1[(wn+hf*16+(mat&1)*8+mrow)*40 + kk + (mat>>1)*8]));
          bf[hf*2+0][0]=r[0]; bf[hf*2+1][0]=r[1];
          bf[hf*2+0][1]=r[2]; bf[hf*2+1][1]=r[3];
        }
        #pragma unroll
        for(int mt=0;mt<2;mt++)
          #pragma unroll
          for(int nt=0;nt<8;nt++)
            MMA16816(acc[mt][nt],af[mt][0],bf[nt][0],bf[nt][1]);
      }
    }
    __syncthreads();
    if(i+2<niter) loadST(st,(i+2)*32);
    CPCOMMIT();
  }
  float scl=1.f;
  if(scaleSlot>=0){float a0,a1,a2; get_params(2,scaleSlot,a0,a1,a2); scl=a2;}
  float lmn=FLT_MAX,lmx=-FLT_MAX;
  float umn=FLT_MAX,umx=-FLT_MAX;
  #pragma unroll
  for(int mt=0;mt<2;mt++){
    float rmnA=FLT_MAX,rmnB=FLT_MAX;
    int rA=m0+wm+mt*16+g;
    #pragma unroll
    for(int nt=0;nt<8;nt++){
      int c=n0+wn+nt*8+t4*2;
      float v0=acc[mt][nt][0]*scl, v1=acc[mt][nt][1]*scl;
      float v2=acc[mt][nt][2]*scl, v3=acc[mt][nt][3]*scl;
      C[(size_t)rA*ldc+c]=v0; C[(size_t)rA*ldc+c+1]=v1;
      C[(size_t)(rA+8)*ldc+c]=v2; C[(size_t)(rA+8)*ldc+c+1]=v3;
      lmn=fminf(fminf(lmn,fminf(v0,v1)),fminf(v2,v3));
      lmx=fmaxf(fmaxf(lmx,fmaxf(v0,v1)),fmaxf(v2,v3));
      if(batch==1){
        rmnA=fminf(rmnA,fminf(v0,v1)); rmnB=fminf(rmnB,fminf(v2,v3));
        if(c<=rA){umn=fminf(umn,v0);umx=fmaxf(umx,v0);}
        if(c+1<=rA){umn=fminf(umn,v1);umx=fmaxf(umx,v1);}
        if(c<=rA+8){umn=fminf(umn,v2);umx=fmaxf(umx,v2);}
        if(c+1<=rA+8){umn=fminf(umn,v3);umx=fmaxf(umx,v3);}
      }
    }
    if(batch==1){
      rmnA=fminf(rmnA,__shfl_xor_sync(0xffffffffu,rmnA,1));
      rmnA=fminf(rmnA,__shfl_xor_sync(0xffffffffu,rmnA,2));
      rmnB=fminf(rmnB,__shfl_xor_sync(0xffffffffu,rmnB,1));
      rmnB=fminf(rmnB,__shfl_xor_sync(0xffffffffu,rmnB,2));
      if(t4==0){
        atomicMinF(&g_amin[z*Sn+rA],rmnA);
        atomicMinF(&g_amin[z*Sn+rA+8],rmnB);
      }
    }
  }
  if(sOut>=0) red_minmax_atomic(lmn,lmx,sOut);
  if(batch==1) red_minmax_atomic(umn,umx,S_UNM);
}

// ---------- AV (NN): A = raw probs f32, fq via reciprocal-multiply in-kernel ----------
__global__ __launch_bounds__(256) void mma_av(
  const float* __restrict__ Praw,const __nv_bfloat16* __restrict__ Vq,
  float* __restrict__ C)
{
  extern __shared__ __nv_bfloat16 sm[];
  __nv_bfloat16* Abase=sm;
  __nv_bfloat16* Vbase=sm+4*ASZ;
  float* Fbase=(float*)(sm+4*ASZ+2*VSZ);
  int z=blockIdx.z,b=z>>4,h=z&15,h2=h>>1;
  Praw+=(size_t)z*Sn*Sn;
  Vq+=(size_t)b*Sn*KNn + h2*Dn;
  C +=(size_t)b*Sn*QNn + h*Dn;
  int tid=threadIdx.x, lane=tid&31, w=tid>>5;
  int wm=(w&3)*32, wn=(w>>2)*64;
  int g=lane>>2, t4=lane&3;
  int m0=blockIdx.y*128;
  int mat=lane>>3, mrow=lane&7;
  float p0,p1_,pd; get_params(1,S_P,p0,p1_,pd);
  float pscale=fmaxf((p1_-p0)/65535.0f,FQEPS);
  float rps=1.0f/pscale;
  float zpp=rintf(-p0/pscale);
  float acc[2][8][4];
  #pragma unroll
  for(int i=0;i<2;i++)
    #pragma unroll
    for(int j=0;j<8;j++)
      #pragma unroll
      for(int r=0;r<4;r++) acc[i][j][r]=0.f;
  auto loadST=[&](int st,int k0){
    #pragma unroll
    for(int rep=0;rep<4;rep++){
      int c=tid+rep*256; int row=c>>3, cc=(c&7)*4;
      cpa16(&Fbase[st*FSZ+row*32+cc],Praw+(size_t)(m0+row)*Sn+k0+cc);
    }
    #pragma unroll
    for(int rep=0;rep<2;rep++){
      int c=tid+rep*256; int vr=c>>4, vc=(c&15)*8;
      cpa16(&Vbase[st*VSZ+vr*136+vc],Vq+(size_t)(k0+vr)*KNn+vc);
    }
  };
  loadST(0,0); CPCOMMIT();
  loadST(1,32); CPCOMMIT();
  int niter=Sn/32;
  for(int i=0;i<niter;i++){
    CPWAIT1(); __syncthreads();
    int st=i&1;
    #pragma unroll
    for(int rep=0;rep<16;rep++){
      int c=tid+rep*256; int row=c>>5, k=c&31;
      float p=Fbase[st*FSZ+row*32+k];
      float q=fminf(fmaxf(rintf(p*rps)+zpp,0.0f),65535.0f);
      float v=(q-zpp)*pscale;
      __nv_bfloat16 hh,ll; split_bf(v,hh,ll);
      Abase[(st*2+0)*ASZ+row*40+k]=hh;
      Abase[(st*2+1)*ASZ+row*40+k]=ll;
    }
    __syncthreads();
    const __nv_bfloat16* As0=Abase+(st*2+0)*ASZ;
    const __nv_bfloat16* As1=Abase+(st*2+1)*ASZ;
    const __nv_bfloat16* Vs=Vbase+st*VSZ;
    #pragma unroll
    for(int kk=0;kk<32;kk+=16){
      unsigned af[2][2][4];
      #pragma unroll
      for(int mt=0;mt<2;mt++){
        ldsm4(af[mt][0],sptr(&As0[(wm+mt*16+(mat&1)*8+mrow)*40 + kk + (mat>>1)*8]));
        ldsm4(af[mt][1],sptr(&As1[(wm+mt*16+(mat&1)*8+mrow)*40 + kk + (mat>>1)*8]));
      }
      unsigned bf[8][2];
      #pragma unroll
      for(int hf=0;hf<4;hf++){
        unsigned r[4];
        ldsm4t(r,sptr(&Vs[(kk+(mat>>1)*8+mrow)*136 + wn + hf*16 + (mat&1)*8]));
        bf[hf*2+0][0]=r[0]; bf[hf*2+1][0]=r[1];
        bf[hf*2+0][1]=r[2]; bf[hf*2+1][1]=r[3];
      }
      #pragma unroll
      for(int mt=0;mt<2;mt++)
        #pragma unroll
        for(int nt=0;nt<8;nt++){
          MMA16816(acc[mt][nt],af[mt][0],bf[nt][0],bf[nt][1]);
          MMA16816(acc[mt][nt],af[mt][1],bf[nt][0],bf[nt][1]);
        }
    }
    __syncthreads();
    if(i+2<niter) loadST(st,(i+2)*32);
    CPCOMMIT();
  }
  float a0,a1,scl; get_params(2,S_V,a0,a1,scl);
  float lmn=FLT_MAX,lmx=-FLT_MAX;
  #pragma unroll
  for(int mt=0;mt<2;mt++)
    #pragma unroll
    for(int nt=0;nt<8;nt++){
      int r0=m0+wm+mt*16+g, c=wn+nt*8+t4*2;
      float v0=acc[mt][nt][0]*scl, v1=acc[mt][nt][1]*scl;
      float v2=acc[mt][nt][2]*scl, v3=acc[mt][nt][3]*scl;
      C[(size_t)r0*QNn+c]=v0; C[(size_t)r0*QNn+c+1]=v1;
      C[(size_t)(r0+8)*QNn+c]=v2; C[(size_t)(r0+8)*QNn+c+1]=v3;
      lmn=fminf(fminf(lmn,fminf(v0,v1)),fminf(v2,v3));
      lmx=fmaxf(fmaxf(lmx,fmaxf(v0,v1)),fmaxf(v2,v3));
    }
  red_minmax_atomic(lmn,lmx,S_CTX);
}

__global__ void k_aminred(const float* __restrict__ amin){
  int i=blockIdx.x*256+threadIdx.x;
  float v=amin[i];
  red_minmax_atomic(v,v,S_AMIN);
  int s=i%Sn;
  float m2n=(s<Sn-1)?v:FLT_MAX, m2x=(s<Sn-1)?v:-FLT_MAX;
  red_minmax_atomic(m2n,m2x,S_AMIN2);
}

// k_p2: masked-half skipped; softmax with reciprocal-multiply
__global__ void k_p2(float* __restrict__ sc,const float* __restrict__ amin){
  int row=blockIdx.x; int s=row%Sn;
  int nmask=Sn-1-s;
  float mnS=g_red[2*S_SC],mxS=g_red[2*S_SC+1];
  float q0=fminf(mnS,0.f),q1=fmaxf(mxS,0.f);
  float scal=(float)(0.08838834764831843);
  float scq=fq_range_d(scal,fminf(scal,0.f),fmaxf(scal,0.f));
  float lo=fq_range_d(mnS,q0,q1)*scq,hi=fq_range_d(mxS,q0,q1)*scq;
  float r0=fminf(lo,0.f),r1=fmaxf(hi,0.f);
  float anr=g_red[2*S_AMIN],axr=g_red[2*S_AMIN+1];
  float an=fq_range_d(fq_range_d(anr,q0,q1)*scq,r0,r1);
  float ax=fq_range_d(fq_range_d(axr,q0,q1)*scq,r0,r1);
  float a0=fminf(an,0.f),a1=fmaxf(ax,0.f);
  float c20=fq_range_d(-20.0f,-20.0f,0.0f);
  float tn=fq_range_d(an,a0,a1)+c20,tx2=fq_range_d(ax,a0,a1)+c20;
  float v0=fminf(tn,0.f),v1=fmaxf(tx2,0.f);
  float a2nr=g_red[2*S_AMIN2],a2xr=g_red[2*S_AMIN2+1];
  float a2n=fq_range_d(fq_range_d(a2nr,q0,q1)*scq,r0,r1);
  float a2x=fq_range_d(fq_range_d(a2xr,q0,q1)*scq,r0,r1);
  float vlo=fq_range_d(fq_range_d(a2n,a0,a1)+c20,v0,v1);
  float vhi=fq_range_d(fq_range_d(a2x,a0,a1)+c20,v0,v1);
  float unr=g_red[2*S_UNM],uxr=g_red[2*S_UNM+1];
  float un=fq_range_d(fq_range_d(unr,q0,q1)*scq,r0,r1);
  float ux=fq_range_d(fq_range_d(uxr,q0,q1)*scq,r0,r1);
  float m0=fminf(fminf(un,vlo),0.f),m1=fmaxf(fmaxf(ux,vhi),0.f);
  float am=fq_range_d(fq_range_d(amin[row],q0,q1)*scq,r0,r1);
  float vv=fq_range_d(fq_range_d(am,a0,a1)+c20,v0,v1);
  float vm=fq_range_d(vv,m0,m1);
  size_t base=(size_t)row*Sn;
  int t0=threadIdx.x*4;
  float x[4]={0,0,0,0};
  float lmx=-FLT_MAX;
  if(t0<=s){
    float4 xv=*(const float4*)&sc[base+t0];
    float xi[4]={xv.x,xv.y,xv.z,xv.w};
    #pragma unroll
    for(int j=0;j<4;j++){
      if(t0+j<=s){
        float a=fq_range_d(fq_range_d(xi[j],q0,q1)*scq,r0,r1);
        x[j]=fq_range_d(a,m0,m1);
        lmx=fmaxf(lmx,x[j]);
      }
    }
  }
  if(nmask>0) lmx=fmaxf(lmx,vm);
  float m=blk_max_b(lmx);
  float ls=0.f;
  #pragma unroll
  for(int j=0;j<4;j++){
    if(t0+j<=s){ x[j]=expf(x[j]-m); ls+=x[j]; }
  }
  float sum=blk_sum_b(ls);
  float evm=(nmask>0)?expf(vm-m):0.f;
  sum+= (float)nmask*evm;
  float rsum=1.0f/sum;
  float pv=evm*rsum;
  float pn=FLT_MAX,px=-FLT_MAX;
  float o[4];
  #pragma unroll
  for(int j=0;j<4;j++){
    float p=(t0+j<=s)?(x[j]*rsum):pv;
    o[j]=p;
    pn=fminf(pn,p); px=fmaxf(px,p);
  }
  *(float4*)&sc[base+t0]=make_float4(o[0],o[1],o[2],o[3]);
  red_minmax_atomic(pn,px,S_P);
}

extern "C" void kernel_launch(void* const* d_in,const int* in_sizes,int n_in,
                              void* d_out,int out_size){
  const float* hs  =(const float*)d_in[0];
  const float* cosb=(const float*)d_in[1];
  const float* sinb=(const float*)d_in[2];
  const float* Wq  =(const float*)d_in[4];
  const float* Wk  =(const float*)d_in[5];
  const float* Wv  =(const float*)d_in[6];
  const float* Wo  =(const float*)d_in[7];
  const float* qw  =(const float*)d_in[8];
  const float* kw  =(const float*)d_in[9];
  float* out=(float*)d_out;

  int SM_T=8*ASZ*2;
  int SM_F=6*ASZ*2;
  int SM_AV=4*ASZ*2+2*VSZ*2+2*FSZ*4;
  static int smset=0;
  if(!smset){
    cudaFuncSetAttribute(mma_nt<true>, cudaFuncAttributeMaxDynamicSharedMemorySize, SM_T);
    cudaFuncSetAttribute(mma_nt<false>,cudaFuncAttributeMaxDynamicSharedMemorySize, SM_F);
    cudaFuncSetAttribute(mma_qkv,      cudaFuncAttributeMaxDynamicSharedMemorySize, SM_T);
    cudaFuncSetAttribute(mma_av,       cudaFuncAttributeMaxDynamicSharedMemorySize, SM_AV);
    smset=1;
  }

  float *pLin,*pLinK,*pQr,*pKr,*pV,*pCtx,*pSc,*pAmin;
  __nv_bfloat16 *pHsh,*pHsl,*pWAh,*pWAl,*pWoh,*pWol;
  __nv_bfloat16 *pQh,*pQl,*pKq,*pVq,*pCh,*pCl;
  cudaGetSymbolAddress((void**)&pLin,g_lin);
  cudaGetSymbolAddress((void**)&pLinK,g_link);
  cudaGetSymbolAddress((void**)&pQr,g_qr);
  cudaGetSymbolAddress((void**)&pKr,g_kr);
  cudaGetSymbolAddress((void**)&pV,g_v);
  cudaGetSymbolAddress((void**)&pCtx,g_ctx);
  cudaGetSymbolAddress((void**)&pSc,g_scores);
  cudaGetSymbolAddress((void**)&pAmin,g_amin);
  cudaGetSymbolAddress((void**)&pHsh,g_hsh); cudaGetSymbolAddress((void**)&pHsl,g_hsl);
  cudaGetSymbolAddress((void**)&pWAh,g_wAh); cudaGetSymbolAddress((void**)&pWAl,g_wAl);
  cudaGetSymbolAddress((void**)&pWoh,g_woh); cudaGetSymbolAddress((void**)&pWol,g_wol);
  cudaGetSymbolAddress((void**)&pQh,g_qh); cudaGetSymbolAddress((void**)&pQl,g_ql);
  cudaGetSymbolAddress((void**)&pKq,g_kq8); cudaGetSymbolAddress((void**)&pVq,g_vq8);
  cudaGetSymbolAddress((void**)&pCh,g_ch); cudaGetSymbolAddress((void**)&pCl,g_cl);

  k_init<<<NROWS/256,256>>>(pAmin);
  k_wsplit4<<<NW4/256,256>>>(Wq,Wk,Wv,Wo,pWAh,pWAl,pWoh,pWol);
  k_minmax<<<1024,256>>>(hs,N_HS,S_HS);
  k_fqsplit<<<2048,256>>>(hs,pHsh,pHsl,N_HS,S_HS);
  // fused QKV projections
  mma_qkv<<<dim3(32,Mn/128),256,SM_T>>>(pHsh,pHsl,pWAh,pWAl,pLin,pLinK,pV);
  // Q path
  k_rms<<<Mn*NHn,128>>>(pLin,qw,S_QLIN,S_QRMS,S_QRMS2);
  k_rope1<<<2048,256>>>(pLin,cosb,sinb,NHn,N_Q,S_QRMS,S_QRMS2,S_QP1,S_QP2);
  k_rope2<<<2048,256>>>(pLin,cosb,sinb,pQr,NHn,N_Q,S_QRMS,S_QRMS2,S_QP1,S_QP2,S_QSUM);
  k_fqsplit<<<2048,256>>>(pQr,pQh,pQl,N_Q,S_QSUM);
  // K path
  k_rms<<<Mn*NKVn,128>>>(pLinK,kw,S_KLIN,S_KRMS,S_KRMS2);
  k_rope1<<<1024,256>>>(pLinK,cosb,sinb,NKVn,N_K,S_KRMS,S_KRMS2,S_KP1,S_KP2);
  k_rope2<<<1024,256>>>(pLinK,cosb,sinb,pKr,NKVn,N_K,S_KRMS,S_KRMS2,S_KP1,S_KP2,S_KSUM);
  k_fq8q<<<1024,256>>>(pKr,pKq,N_K,S_KSUM);
  // V path
  k_fq8q<<<1024,256>>>(pV,pVq,N_K,S_V);
  // scores GEMM + fused raw reductions
  mma_nt<false><<<dim3(Sn/128,Sn/128,Bn*NHn),256,SM_F>>>(pQh,pQl,pKq,pKq,pSc,Dn,Dn,Dn,Sn,S_SC,S_KSUM,1);
  k_aminred<<<NROWS/256,256>>>(pAmin);
  k_p2<<<NROWS,256>>>(pSc,pAmin);
  if(out_size>=(int)(OUT_MAIN+N_SC))
    k_pattn<<<NROWS,256>>>(pSc,out+OUT_MAIN);
  // AV + output proj
  mma_av<<<dim3(1,Sn/128,Bn*NHn),256,SM_AV>>>(pSc,pVq,pCtx);
  k_fqsplit<<<2048,256>>>(pCtx,pCh,pCl,N_Q,S_CTX);
  mma_nt<true><<<dim3(HIDn/128,Mn/128,1),256,SM_T>>>(pCh,pCl,pWoh,pWol,out,QNn,QNn,QNn,HIDn,-1,-1,0);
}